// round 13
// baseline (speedup 1.0000x reference)
#include <cuda_runtime.h>
#include <math.h>

#define G 2048
#define E 512
#define B 16

// ---------------- device scratch ----------------
__device__ float g_q0[E], g_q1[E], g_k0v[E], g_k1v[E];
__device__ float g_S[4];                      // S[a*2+c] = q_a . k_c
__device__ __align__(16) unsigned g_bits[G];  // bit b = xbin[b, g]
__device__ float g_lr3;
__device__ __align__(16) float g_upart[128 * G]; // u partials (128 slabs of 16 rows)
__device__ __align__(16) float g_u[G];           // fcCox_w @ fc1_w

__device__ __forceinline__ float lrelu(float x) { return x > 0.f ? x : 0.01f * x; }

// ---------------- kernel 1: qk projections + prep + u partials -----------
// (exact R9/R12 — measured 7.8us)
__global__ void qk_kernel(const float* __restrict__ embMat,
                          const float* __restrict__ Wq,
                          const float* __restrict__ Wk,
                          const int* __restrict__ datax,
                          const float* __restrict__ k3,
                          const float* __restrict__ fc1w,
                          const float* __restrict__ fcCox) {
    int tid = threadIdx.x;        // 256
    int f = blockIdx.x;

    if (f >= 512) {               // ---- u partials: 256 blocks ----
        int bu = f - 512;                     // 0..255
        int s  = bu >> 1;                     // slab 0..127 (16 fc1 rows each)
        int c4 = (bu & 1) * 256 + tid;        // float4 column 0..511
        const float4* base = (const float4*)fc1w + (size_t)(s * 16) * 512 + c4;
        const float* cw = fcCox + s * 16;
        float4 acc = make_float4(0.f, 0.f, 0.f, 0.f);
#pragma unroll
        for (int j = 0; j < 16; j++) {
            float4 v = base[(size_t)j * 512];
            float c = cw[j];
            acc.x += c * v.x; acc.y += c * v.y;
            acc.z += c * v.z; acc.w += c * v.w;
        }
        ((float4*)g_upart)[s * 512 + c4] = acc;
        return;
    }

    if (f < 8) {                  // ---- folded prep ----
        int g = f * 256 + tid;
        unsigned bits = 0;
#pragma unroll
        for (int b = 0; b < B; b++)
            bits |= (datax[b * G + g] != 0 ? 1u : 0u) << b;
        g_bits[g] = bits;
        if (f == 0 && tid == 0) g_lr3 = lrelu(k3[0]);
    }

    // ---- q/k projection for feature f ----
    const float* wq = Wq + (size_t)f * E;
    const float* wk = Wk + (size_t)f * E;
    float s0q = 0.f, s1q = 0.f, s0k = 0.f, s1k = 0.f;
#pragma unroll
    for (int i = 0; i < 2; i++) {
        int e = tid + i * 256;
        float e0 = embMat[e], e1 = embMat[E + e];
        float wqe = wq[e], wke = wk[e];
        s0q += e0 * wqe; s1q += e1 * wqe;
        s0k += e0 * wke; s1k += e1 * wke;
    }
#pragma unroll
    for (int o = 16; o > 0; o >>= 1) {
        s0q += __shfl_down_sync(~0u, s0q, o);
        s1q += __shfl_down_sync(~0u, s1q, o);
        s0k += __shfl_down_sync(~0u, s0k, o);
        s1k += __shfl_down_sync(~0u, s1k, o);
    }
    __shared__ float red[8][4];
    int w = tid >> 5, l = tid & 31;
    if (l == 0) { red[w][0] = s0q; red[w][1] = s1q; red[w][2] = s0k; red[w][3] = s1k; }
    __syncthreads();
    if (tid == 0) {
        float a = 0, b = 0, c = 0, d = 0;
        for (int i = 0; i < 8; i++) { a += red[i][0]; b += red[i][1]; c += red[i][2]; d += red[i][3]; }
        g_q0[f] = a; g_q1[f] = b; g_k0v[f] = c; g_k1v[f] = d;
    }
}

// ---------------- kernel 2: S table + C + u reduce -----------------------
__global__ void s_kernel(const float* __restrict__ fc1b,
                         const float* __restrict__ fcCox,
                         float* __restrict__ out) {
    int t = threadIdx.x;          // 512

    if (blockIdx.x > 0) {         // ---- u reduce (128 slabs) ----
        if (t < 256) {
            int c4 = (blockIdx.x - 1) * 256 + t;   // 0..511
            float4 acc = make_float4(0.f, 0.f, 0.f, 0.f);
#pragma unroll 16
            for (int s = 0; s < 128; s++) {
                float4 v = ((const float4*)g_upart)[s * 512 + c4];
                acc.x += v.x; acc.y += v.y; acc.z += v.z; acc.w += v.w;
            }
            ((float4*)g_u)[c4] = acc;
        }
        return;
    }

    float q0 = g_q0[t], q1 = g_q1[t], k0 = g_k0v[t], k1 = g_k1v[t];
    float p0 = q0 * k0, p1 = q0 * k1, p2 = q1 * k0, p3 = q1 * k1;
    float c0 = 0.f;
#pragma unroll
    for (int i = 0; i < 4; i++) {
        int g = t + i * 512;
        c0 += fc1b[g] * fcCox[g];
    }
#pragma unroll
    for (int o = 16; o > 0; o >>= 1) {
        p0 += __shfl_down_sync(~0u, p0, o);
        p1 += __shfl_down_sync(~0u, p1, o);
        p2 += __shfl_down_sync(~0u, p2, o);
        p3 += __shfl_down_sync(~0u, p3, o);
        c0 += __shfl_down_sync(~0u, c0, o);
    }
    __shared__ float red[16][5];
    int w = t >> 5, l = t & 31;
    if (l == 0) { red[w][0] = p0; red[w][1] = p1; red[w][2] = p2; red[w][3] = p3; red[w][4] = c0; }
    __syncthreads();
    if (t == 0) {
        float a = 0, b = 0, c = 0, d = 0, e = 0;
        for (int i = 0; i < 16; i++) { a += red[i][0]; b += red[i][1]; c += red[i][2]; d += red[i][3]; e += red[i][4]; }
        g_S[0] = a; g_S[1] = b; g_S[2] = c; g_S[3] = d;
        red[0][4] = e;
    }
    __syncthreads();
    if (t < B) out[t] = red[0][4];   // out[b] = C; big_kernel atomicAdds the rest
}

// ---------------- kernel 3: fused bias + origin write + softmax + output -
// TWO adjacent g-rows per block; per plane each block stores 4 float4s per
// thread covering one contiguous 16KB span (rows 2g,2g+1 x chunks 0,1) —
// doubling R12's winning 8KB store burst. Accumulation is row-sequential
// with the champion single-reduce-pass structure.
__global__ void __launch_bounds__(256, 2)
big_kernel(const float* __restrict__ k1m, const float* __restrict__ k2m,
           const float* __restrict__ spm, const float* __restrict__ cmm,
           const float* __restrict__ padm, float* __restrict__ out) {
    int g0 = blockIdx.x * 2;
    int tid = threadIdx.x;        // 256
    __shared__ float sAcc[2][2 * B];
    if (tid < 2 * B) { sAcc[0][tid] = 0.f; sAcc[1][tid] = 0.f; }
    __syncthreads();

    float lr3 = g_lr3;
    float s00 = g_S[0], s01 = g_S[1], s10 = g_S[2], s11 = g_S[3];
    unsigned gb0 = g_bits[g0], gb1 = g_bits[g0 + 1];

    size_t rowoff = (size_t)g0 * G;

    float4 bias[2][2];            // [row][chunk]
    uint4 hb[2];                  // shared across rows
#pragma unroll
    for (int r = 0; r < 2; r++) {
        const float4* r1 = (const float4*)(k1m + rowoff + r * G);
        const float4* r2 = (const float4*)(k2m + rowoff + r * G);
        const float4* rs = (const float4*)(spm + rowoff + r * G);
        const float4* rc = (const float4*)(cmm + rowoff + r * G);
        const float4* rp = (const float4*)(padm + rowoff + r * G);
#pragma unroll
        for (int i = 0; i < 2; i++) {
            int h4 = tid + i * 256;
            float4 v1 = r1[h4], v2 = r2[h4], vs = rs[h4], vc = rc[h4], vp = rp[h4];
            float4 bv;
            bv.x = lrelu(v1.x) * vs.x + lrelu(v2.x) * vc.x + lr3 * vp.x;
            bv.y = lrelu(v1.y) * vs.y + lrelu(v2.y) * vc.y + lr3 * vp.y;
            bv.z = lrelu(v1.z) * vs.z + lrelu(v2.z) * vc.z + lr3 * vp.z;
            bv.w = lrelu(v1.w) * vs.w + lrelu(v2.w) * vc.w + lr3 * vp.w;
            bias[r][i] = bv;
            if (r == 0) hb[i] = ((const uint4*)g_bits)[h4];
        }
    }

    // single plane loop: 16KB contiguous span per block per plane
    float* ob = out + 16 + rowoff + (size_t)tid * 4;
#pragma unroll
    for (int b = 0; b < B; b++) {
        int a0b = (gb0 >> b) & 1;
        int a1b = (gb1 >> b) & 1;
        float r0a0 = a0b ? s10 : s00, r0a1 = a0b ? s11 : s01;
        float r1a0 = a1b ? s10 : s00, r1a1 = a1b ? s11 : s01;
        float* pb = ob + (size_t)b * ((size_t)G * G);
#pragma unroll
        for (int i = 0; i < 2; i++) {
            float4 o0, o1;
            o0.x = bias[0][i].x + (((hb[i].x >> b) & 1) ? r0a1 : r0a0);
            o0.y = bias[0][i].y + (((hb[i].y >> b) & 1) ? r0a1 : r0a0);
            o0.z = bias[0][i].z + (((hb[i].z >> b) & 1) ? r0a1 : r0a0);
            o0.w = bias[0][i].w + (((hb[i].w >> b) & 1) ? r0a1 : r0a0);
            o1.x = bias[1][i].x + (((hb[i].x >> b) & 1) ? r1a1 : r1a0);
            o1.y = bias[1][i].y + (((hb[i].y >> b) & 1) ? r1a1 : r1a0);
            o1.z = bias[1][i].z + (((hb[i].z >> b) & 1) ? r1a1 : r1a0);
            o1.w = bias[1][i].w + (((hb[i].w >> b) & 1) ? r1a1 : r1a0);
            *((float4*)(pb + (size_t)i * 1024)) = o0;
            *((float4*)(pb + (size_t)i * 1024 + G)) = o1;
        }
    }

    // raw exps in place of bias (ratio is shift-invariant, range safe)
#pragma unroll
    for (int r = 0; r < 2; r++)
#pragma unroll
        for (int i = 0; i < 2; i++) {
            bias[r][i].x = __expf(bias[r][i].x);
            bias[r][i].y = __expf(bias[r][i].y);
            bias[r][i].z = __expf(bias[r][i].z);
            bias[r][i].w = __expf(bias[r][i].w);
        }

    // row-sequential accumulation (t0/t1 reused across rows)
#pragma unroll
    for (int r = 0; r < 2; r++) {
        float t1[B], t0[B];
#pragma unroll
        for (int b = 0; b < B; b++) { t1[b] = 0.f; t0[b] = 0.f; }
#pragma unroll
        for (int i = 0; i < 2; i++) {
            float e0 = bias[r][i].x, e1 = bias[r][i].y;
            float e2 = bias[r][i].z, e3 = bias[r][i].w;
#pragma unroll
            for (int b = 0; b < B; b++) {
                float m0 = ((hb[i].x >> b) & 1) ? e0 : 0.f;
                float m1 = ((hb[i].y >> b) & 1) ? e1 : 0.f;
                float m2 = ((hb[i].z >> b) & 1) ? e2 : 0.f;
                float m3 = ((hb[i].w >> b) & 1) ? e3 : 0.f;
                t1[b] += (m0 + m1) + (m2 + m3);
                t0[b] += ((e0 - m0) + (e1 - m1)) + ((e2 - m2) + (e3 - m3));
            }
        }
#pragma unroll
        for (int o = 16; o > 0; o >>= 1) {
#pragma unroll
            for (int b = 0; b < B; b++) {
                t1[b] += __shfl_down_sync(~0u, t1[b], o);
                t0[b] += __shfl_down_sync(~0u, t0[b], o);
            }
        }
        if ((tid & 31) == 0) {
#pragma unroll
            for (int b = 0; b < B; b++) {
                atomicAdd(&sAcc[r][b], t1[b]);
                atomicAdd(&sAcc[r][B + b], t0[b]);
            }
        }
    }
    __syncthreads();

    // ---- output tail: both rows' contributions to out[b] ----
    if (tid < 2 * B) {
        int r = tid >> 4;
        int b = tid & 15;
        int g = g0 + r;
        unsigned gb = r ? gb1 : gb0;
        float T1 = sAcc[r][b];
        float T0 = sAcc[r][B + b];
        unsigned A = (gb >> b) & 1u;
        float sa0 = A ? s10 : s00;
        float sa1 = A ? s11 : s01;
        float mm = fmaxf(sa0, sa1);
        float f0 = __expf(sa0 - mm);
        float f1 = __expf(sa1 - mm);
        float num = f1 * T1;
        float den = f0 * T0 + num;
        float y = (float)A + num / den;
        atomicAdd(&out[b], y * g_u[g]);
    }
}

// ---------------- launch ----------------
extern "C" void kernel_launch(void* const* d_in, const int* in_sizes, int n_in,
                              void* d_out, int out_size) {
    const int*   datax  = (const int*)d_in[0];
    const float* embMat = (const float*)d_in[1];
    const float* Wq     = (const float*)d_in[2];
    const float* Wk     = (const float*)d_in[3];
    const float* k1     = (const float*)d_in[4];
    const float* k2     = (const float*)d_in[5];
    const float* k3     = (const float*)d_in[6];
    const float* sp     = (const float*)d_in[7];
    const float* cm     = (const float*)d_in[8];
    const float* pad    = (const float*)d_in[9];
    const float* fc1w   = (const float*)d_in[10];
    const float* fc1b   = (const float*)d_in[11];
    const float* fcCox  = (const float*)d_in[12];
    float* out = (float*)d_out;

    qk_kernel<<<768, 256>>>(embMat, Wq, Wk, datax, k3, fc1w, fcCox);
    s_kernel<<<3, 512>>>(fc1b, fcCox, out);
    big_kernel<<<G / 2, 256>>>(k1, k2, sp, cm, pad, out);
}

// round 14
// speedup vs baseline: 2.2491x; 2.2491x over previous
#include <cuda_runtime.h>
#include <math.h>

#define G 2048
#define E 512
#define B 16

// ---------------- device scratch ----------------
__device__ float g_q0[E], g_q1[E], g_k0v[E], g_k1v[E];
__device__ float g_S[4];                      // S[a*2+c] = q_a . k_c
__device__ __align__(16) unsigned g_bits[G];  // bit b = xbin[b, g]
__device__ float g_lr3;
__device__ __align__(16) float g_upart[128 * G]; // u partials (128 slabs of 16 rows)
__device__ __align__(16) float g_u[G];           // fcCox_w @ fc1_w

__device__ __forceinline__ float lrelu(float x) { return x > 0.f ? x : 0.01f * x; }

// ---------------- kernel 1: qk projections + prep + u partials -----------
// (exact R9/R12 — measured 7.8us)
__global__ void qk_kernel(const float* __restrict__ embMat,
                          const float* __restrict__ Wq,
                          const float* __restrict__ Wk,
                          const int* __restrict__ datax,
                          const float* __restrict__ k3,
                          const float* __restrict__ fc1w,
                          const float* __restrict__ fcCox) {
    int tid = threadIdx.x;        // 256
    int f = blockIdx.x;

    if (f >= 512) {               // ---- u partials: 256 blocks ----
        int bu = f - 512;                     // 0..255
        int s  = bu >> 1;                     // slab 0..127 (16 fc1 rows each)
        int c4 = (bu & 1) * 256 + tid;        // float4 column 0..511
        const float4* base = (const float4*)fc1w + (size_t)(s * 16) * 512 + c4;
        const float* cw = fcCox + s * 16;
        float4 acc = make_float4(0.f, 0.f, 0.f, 0.f);
#pragma unroll
        for (int j = 0; j < 16; j++) {
            float4 v = base[(size_t)j * 512];
            float c = cw[j];
            acc.x += c * v.x; acc.y += c * v.y;
            acc.z += c * v.z; acc.w += c * v.w;
        }
        ((float4*)g_upart)[s * 512 + c4] = acc;
        return;
    }

    if (f < 8) {                  // ---- folded prep ----
        int g = f * 256 + tid;
        unsigned bits = 0;
#pragma unroll
        for (int b = 0; b < B; b++)
            bits |= (datax[b * G + g] != 0 ? 1u : 0u) << b;
        g_bits[g] = bits;
        if (f == 0 && tid == 0) g_lr3 = lrelu(k3[0]);
    }

    // ---- q/k projection for feature f ----
    const float* wq = Wq + (size_t)f * E;
    const float* wk = Wk + (size_t)f * E;
    float s0q = 0.f, s1q = 0.f, s0k = 0.f, s1k = 0.f;
#pragma unroll
    for (int i = 0; i < 2; i++) {
        int e = tid + i * 256;
        float e0 = embMat[e], e1 = embMat[E + e];
        float wqe = wq[e], wke = wk[e];
        s0q += e0 * wqe; s1q += e1 * wqe;
        s0k += e0 * wke; s1k += e1 * wke;
    }
#pragma unroll
    for (int o = 16; o > 0; o >>= 1) {
        s0q += __shfl_down_sync(~0u, s0q, o);
        s1q += __shfl_down_sync(~0u, s1q, o);
        s0k += __shfl_down_sync(~0u, s0k, o);
        s1k += __shfl_down_sync(~0u, s1k, o);
    }
    __shared__ float red[8][4];
    int w = tid >> 5, l = tid & 31;
    if (l == 0) { red[w][0] = s0q; red[w][1] = s1q; red[w][2] = s0k; red[w][3] = s1k; }
    __syncthreads();
    if (tid == 0) {
        float a = 0, b = 0, c = 0, d = 0;
        for (int i = 0; i < 8; i++) { a += red[i][0]; b += red[i][1]; c += red[i][2]; d += red[i][3]; }
        g_q0[f] = a; g_q1[f] = b; g_k0v[f] = c; g_k1v[f] = d;
    }
}

// ---------------- kernel 2: S table + C + u reduce -----------------------
__global__ void s_kernel(const float* __restrict__ fc1b,
                         const float* __restrict__ fcCox,
                         float* __restrict__ out) {
    int t = threadIdx.x;          // 512

    if (blockIdx.x > 0) {         // ---- u reduce (128 slabs) ----
        if (t < 256) {
            int c4 = (blockIdx.x - 1) * 256 + t;   // 0..511
            float4 acc = make_float4(0.f, 0.f, 0.f, 0.f);
#pragma unroll 16
            for (int s = 0; s < 128; s++) {
                float4 v = ((const float4*)g_upart)[s * 512 + c4];
                acc.x += v.x; acc.y += v.y; acc.z += v.z; acc.w += v.w;
            }
            ((float4*)g_u)[c4] = acc;
        }
        return;
    }

    float q0 = g_q0[t], q1 = g_q1[t], k0 = g_k0v[t], k1 = g_k1v[t];
    float p0 = q0 * k0, p1 = q0 * k1, p2 = q1 * k0, p3 = q1 * k1;
    float c0 = 0.f;
#pragma unroll
    for (int i = 0; i < 4; i++) {
        int g = t + i * 512;
        c0 += fc1b[g] * fcCox[g];
    }
#pragma unroll
    for (int o = 16; o > 0; o >>= 1) {
        p0 += __shfl_down_sync(~0u, p0, o);
        p1 += __shfl_down_sync(~0u, p1, o);
        p2 += __shfl_down_sync(~0u, p2, o);
        p3 += __shfl_down_sync(~0u, p3, o);
        c0 += __shfl_down_sync(~0u, c0, o);
    }
    __shared__ float red[16][5];
    int w = t >> 5, l = t & 31;
    if (l == 0) { red[w][0] = p0; red[w][1] = p1; red[w][2] = p2; red[w][3] = p3; red[w][4] = c0; }
    __syncthreads();
    if (t == 0) {
        float a = 0, b = 0, c = 0, d = 0, e = 0;
        for (int i = 0; i < 16; i++) { a += red[i][0]; b += red[i][1]; c += red[i][2]; d += red[i][3]; e += red[i][4]; }
        g_S[0] = a; g_S[1] = b; g_S[2] = c; g_S[3] = d;
        red[0][4] = e;
    }
    __syncthreads();
    if (t < B) out[t] = red[0][4];   // out[b] = C; big_kernel atomicAdds the rest
}

// ---------------- kernel 3: fused bias + origin write + softmax + output -
// EXACT R12 champion body: one g-row per block, both chunks' bias computed
// first, then a single plane loop stores both chunks back-to-back so each
// plane's 8KB row is one contiguous burst per block. Raw exps (no max pass),
// single reduce pass, output tail fold.
__global__ void __launch_bounds__(256, 2)
big_kernel(const float* __restrict__ k1m, const float* __restrict__ k2m,
           const float* __restrict__ spm, const float* __restrict__ cmm,
           const float* __restrict__ padm, float* __restrict__ out) {
    int g = blockIdx.x;
    int tid = threadIdx.x;        // 256
    __shared__ float sAcc[2 * B];
    if (tid < 2 * B) sAcc[tid] = 0.f;
    __syncthreads();

    unsigned gb = g_bits[g];
    float lr3 = g_lr3;
    float s00 = g_S[0], s01 = g_S[1], s10 = g_S[2], s11 = g_S[3];

    size_t rowoff = (size_t)g * G;
    const float4* r1 = (const float4*)(k1m + rowoff);
    const float4* r2 = (const float4*)(k2m + rowoff);
    const float4* rs = (const float4*)(spm + rowoff);
    const float4* rc = (const float4*)(cmm + rowoff);
    const float4* rp = (const float4*)(padm + rowoff);

    float4 bias[2];
    uint4 hb[2];
#pragma unroll
    for (int i = 0; i < 2; i++) {
        int h4 = tid + i * 256;
        float4 v1 = r1[h4], v2 = r2[h4], vs = rs[h4], vc = rc[h4], vp = rp[h4];
        float4 bv;
        bv.x = lrelu(v1.x) * vs.x + lrelu(v2.x) * vc.x + lr3 * vp.x;
        bv.y = lrelu(v1.y) * vs.y + lrelu(v2.y) * vc.y + lr3 * vp.y;
        bv.z = lrelu(v1.z) * vs.z + lrelu(v2.z) * vc.z + lr3 * vp.z;
        bv.w = lrelu(v1.w) * vs.w + lrelu(v2.w) * vc.w + lr3 * vp.w;
        bias[i] = bv;
        hb[i] = ((const uint4*)g_bits)[h4];
    }

    // single plane loop: both chunks stored back-to-back per plane
    float* ob0 = out + 16 + rowoff + (size_t)tid * 4;
    float* ob1 = ob0 + 1024;      // chunk 1 offset (256 float4 = 1024 floats)
#pragma unroll
    for (int b = 0; b < B; b++) {
        int a = (gb >> b) & 1;
        float a0 = a ? s10 : s00;
        float a1 = a ? s11 : s01;
        float4 o0, o1;
        o0.x = bias[0].x + (((hb[0].x >> b) & 1) ? a1 : a0);
        o0.y = bias[0].y + (((hb[0].y >> b) & 1) ? a1 : a0);
        o0.z = bias[0].z + (((hb[0].z >> b) & 1) ? a1 : a0);
        o0.w = bias[0].w + (((hb[0].w >> b) & 1) ? a1 : a0);
        o1.x = bias[1].x + (((hb[1].x >> b) & 1) ? a1 : a0);
        o1.y = bias[1].y + (((hb[1].y >> b) & 1) ? a1 : a0);
        o1.z = bias[1].z + (((hb[1].z >> b) & 1) ? a1 : a0);
        o1.w = bias[1].w + (((hb[1].w >> b) & 1) ? a1 : a0);
        *((float4*)(ob0 + (size_t)b * ((size_t)G * G))) = o0;
        *((float4*)(ob1 + (size_t)b * ((size_t)G * G))) = o1;
    }

    // raw exps (no max shift; ratio is shift-invariant, range safe)
    float4 ev[2];
#pragma unroll
    for (int i = 0; i < 2; i++) {
        ev[i].x = __expf(bias[i].x);
        ev[i].y = __expf(bias[i].y);
        ev[i].z = __expf(bias[i].z);
        ev[i].w = __expf(bias[i].w);
    }

    float t1[B], t0[B];
#pragma unroll
    for (int b = 0; b < B; b++) { t1[b] = 0.f; t0[b] = 0.f; }
#pragma unroll
    for (int i = 0; i < 2; i++) {
        float e0 = ev[i].x, e1 = ev[i].y, e2 = ev[i].z, e3 = ev[i].w;
#pragma unroll
        for (int b = 0; b < B; b++) {
            float m0 = ((hb[i].x >> b) & 1) ? e0 : 0.f;
            float m1 = ((hb[i].y >> b) & 1) ? e1 : 0.f;
            float m2 = ((hb[i].z >> b) & 1) ? e2 : 0.f;
            float m3 = ((hb[i].w >> b) & 1) ? e3 : 0.f;
            t1[b] += (m0 + m1) + (m2 + m3);
            t0[b] += ((e0 - m0) + (e1 - m1)) + ((e2 - m2) + (e3 - m3));
        }
    }
#pragma unroll
    for (int o = 16; o > 0; o >>= 1) {
#pragma unroll
        for (int b = 0; b < B; b++) {
            t1[b] += __shfl_down_sync(~0u, t1[b], o);
            t0[b] += __shfl_down_sync(~0u, t0[b], o);
        }
    }
    if ((tid & 31) == 0) {
#pragma unroll
        for (int b = 0; b < B; b++) {
            atomicAdd(&sAcc[b], t1[b]);
            atomicAdd(&sAcc[B + b], t0[b]);
        }
    }
    __syncthreads();

    // ---- output tail: this row's contribution to out[b] ----
    if (tid < B) {
        int b = tid;
        float T1 = sAcc[b];
        float T0 = sAcc[B + b];
        unsigned A = (gb >> b) & 1u;
        float sa0 = A ? s10 : s00;
        float sa1 = A ? s11 : s01;
        float mm = fmaxf(sa0, sa1);
        float f0 = __expf(sa0 - mm);
        float f1 = __expf(sa1 - mm);
        float num = f1 * T1;
        float den = f0 * T0 + num;
        float y = (float)A + num / den;
        atomicAdd(&out[b], y * g_u[g]);
    }
}

// ---------------- launch ----------------
extern "C" void kernel_launch(void* const* d_in, const int* in_sizes, int n_in,
                              void* d_out, int out_size) {
    const int*   datax  = (const int*)d_in[0];
    const float* embMat = (const float*)d_in[1];
    const float* Wq     = (const float*)d_in[2];
    const float* Wk     = (const float*)d_in[3];
    const float* k1     = (const float*)d_in[4];
    const float* k2     = (const float*)d_in[5];
    const float* k3     = (const float*)d_in[6];
    const float* sp     = (const float*)d_in[7];
    const float* cm     = (const float*)d_in[8];
    const float* pad    = (const float*)d_in[9];
    const float* fc1w   = (const float*)d_in[10];
    const float* fc1b   = (const float*)d_in[11];
    const float* fcCox  = (const float*)d_in[12];
    float* out = (float*)d_out;

    qk_kernel<<<768, 256>>>(embMat, Wq, Wk, datax, k3, fc1w, fcCox);
    s_kernel<<<3, 512>>>(fc1b, fcCox, out);
    big_kernel<<<G, 256>>>(k1, k2, sp, cm, pad, out);
}